// round 9
// baseline (speedup 1.0000x reference)
#include <cuda_runtime.h>
#include <cuda_fp16.h>
#include <cstdint>

// ---------------------------------------------------------------------------
// out = relu(x·W1effᵀ + b1)·fc2ᵀ + b2   via mma.sync m16n8k16 (fp16 in, fp32 acc)
// B (104x784 fp16, 163KB) resident in smem; A loaded as LDG.128 row-quads and
// redistributed to mma fragment layout with shuffles (no smem for A).
// M=32 rows/warp (2 fragment sets share each B ldmatrix), 14 warps, grid=147
// -> exactly ONE wave, 98.8% warp-slot balance. Barrier-free mainloop.
// ---------------------------------------------------------------------------

#define KW      784
#define NSTEP   49                 // 784 / 16
#define BSTRIDE 3328               // 104 n-rows * 32 B per k-step
#define BSMEM   (NSTEP * BSTRIDE)  // 163072 B
#define CTA_T   448
#define ROWS_W  32

__device__ __half g_w1[104 * KW];

// ---------------- weight fold + fp16 conversion ----------------------------

__global__ void build_w1(const float* __restrict__ conv_w,
                         const float* __restrict__ fc1_w) {
    int idx = blockIdx.x * blockDim.x + threadIdx.x;
    if (idx >= 104 * KW) return;
    int n = idx / KW;
    int k = idx % KW;
    float v = 0.f;
    if (n < 100) {
        int y  = k / 28;
        int xx = k % 28;
        #pragma unroll
        for (int i = 0; i < 3; i++) {
            int r = y - i;
            if (r < 0 || r > 25) continue;
            #pragma unroll
            for (int j = 0; j < 3; j++) {
                int c = xx - j;
                if (c < 0 || c > 25) continue;
                v += fc1_w[n * 676 + r * 26 + c] * conv_w[i * 3 + j];
            }
        }
    }
    g_w1[n * KW + k] = __float2half(v);
}

// ---------------- PTX helpers ----------------------------------------------

__device__ __forceinline__ uint32_t smem_u32(const void* p) {
    uint32_t a;
    asm("{ .reg .u64 t; cvta.to.shared.u64 t, %1; cvt.u32.u64 %0, t; }"
        : "=r"(a) : "l"(p));
    return a;
}

__device__ __forceinline__ void ldsm_x4(uint32_t& r0, uint32_t& r1,
                                        uint32_t& r2, uint32_t& r3, uint32_t addr) {
    asm volatile("ldmatrix.sync.aligned.m8n8.x4.shared.b16 {%0,%1,%2,%3}, [%4];"
        : "=r"(r0), "=r"(r1), "=r"(r2), "=r"(r3) : "r"(addr));
}

__device__ __forceinline__ void ldsm_x2(uint32_t& r0, uint32_t& r1, uint32_t addr) {
    asm volatile("ldmatrix.sync.aligned.m8n8.x2.shared.b16 {%0,%1}, [%2];"
        : "=r"(r0), "=r"(r1) : "r"(addr));
}

__device__ __forceinline__ void mma16816(float* c,
                                         uint32_t a0, uint32_t a1, uint32_t a2, uint32_t a3,
                                         uint32_t b0, uint32_t b1) {
    asm volatile(
        "mma.sync.aligned.m16n8k16.row.col.f32.f16.f16.f32 "
        "{%0,%1,%2,%3}, {%4,%5,%6,%7}, {%8,%9}, {%0,%1,%2,%3};"
        : "+f"(c[0]), "+f"(c[1]), "+f"(c[2]), "+f"(c[3])
        : "r"(a0), "r"(a1), "r"(a2), "r"(a3), "r"(b0), "r"(b1));
}

// ---------------- fused GEMM + epilogue ------------------------------------

__global__ __launch_bounds__(CTA_T, 1)
void fused_gemm(const float* __restrict__ x,
                const float* __restrict__ fc1_b,
                const float* __restrict__ fc2_w,
                const float* __restrict__ fc2_b,
                float* __restrict__ out, int Brows) {
    extern __shared__ __align__(128) uint8_t dynsmem[];   // B: 163072 B
    __shared__ float b1s[128];
    __shared__ float w2s[100][12];
    __shared__ float b2v[16];

    const int tid = threadIdx.x;
    const int wid = tid >> 5;            // 0..13
    const int lid = tid & 31;
    const int qid = lid & 3;
    const int qrow = lid >> 2;           // 0..7
    const int m0 = blockIdx.x * (14 * ROWS_W);
    const int mw = wid * ROWS_W;

    const uint32_t bbase = smem_u32(dynsmem);

    // ---- stage B once: g_w1[n][k] -> [step s][n][2x16B], swizzled
    for (int idx = tid; idx < NSTEP * 104 * 2; idx += CTA_T) {
        int cch = idx & 1;
        int n = (idx >> 1) % 104;
        int s = (idx >> 1) / 104;
        uint32_t dst = bbase + (uint32_t)(s * 104 + n) * 32
                     + ((cch ^ ((n >> 2) & 1)) << 4);
        const __half* src = &g_w1[n * KW + s * 16 + cch * 8];
        asm volatile("cp.async.cg.shared.global [%0], [%1], 16;"
                     :: "r"(dst), "l"(src) : "memory");
    }
    asm volatile("cp.async.commit_group;" ::: "memory");

    if (tid < 128) b1s[tid] = (tid < 100) ? fc1_b[tid] : 0.f;
    if (tid < 100) {
        #pragma unroll
        for (int j = 0; j < 10; j++) w2s[tid][j] = fc2_w[j * 100 + tid];
    }
    if (tid < 10) b2v[tid] = fc2_b[tid];

    // ---- B ldmatrix lane offsets
    const int b_nl = ((lid >> 4) & 1) * 8 + (lid & 7);
    const int b_ko = (lid >> 3) & 1;
    uint32_t boff[6];
    #pragma unroll
    for (int tp = 0; tp < 6; tp++) {
        int n_l = tp * 16 + b_nl;
        boff[tp] = (uint32_t)(n_l * 32 + ((b_ko ^ ((n_l >> 2) & 1)) << 4));
    }
    const int nx = 96 + (lid & 7);
    const uint32_t bxoff = (uint32_t)(nx * 32 + ((b_ko ^ ((nx >> 2) & 1)) << 4));

    // ---- A geometry: LDG.128 row-quads. Group g: row = m0+mw+8g+(lid>>2),
    // lane holds k = s*16 + (lid&3)*4 .. +3 (float4).
    const int rowb = m0 + mw + (lid >> 2);
    const float* xb = x + (size_t)rowb * KW + (lid & 3) * 4;
    bool pg[4];
    #pragma unroll
    for (int g = 0; g < 4; g++) pg[g] = (rowb + 8 * g) < Brows;

    // shuffle sources for fragment rebuild
    const int src0 = (lid & 28) | (qid >> 1);
    const int src1 = src0 + 2;
    const bool hi_half = (qid & 1);

    float c0[13][4], c1[13][4];
    #pragma unroll
    for (int t = 0; t < 13; t++)
        #pragma unroll
        for (int q = 0; q < 4; q++) { c0[t][q] = 0.f; c1[t][q] = 0.f; }

    float4 pf[4];

    #define LOAD_A(s) do {                                                    \
        const float4 z4 = make_float4(0.f, 0.f, 0.f, 0.f);                    \
        pf[0] = pg[0] ? *reinterpret_cast<const float4*>(xb + (s) * 16)             : z4; \
        pf[1] = pg[1] ? *reinterpret_cast<const float4*>(xb + 8 * KW + (s) * 16)    : z4; \
        pf[2] = pg[2] ? *reinterpret_cast<const float4*>(xb + 16 * KW + (s) * 16)   : z4; \
        pf[3] = pg[3] ? *reinterpret_cast<const float4*>(xb + 24 * KW + (s) * 16)   : z4; \
    } while (0)

    LOAD_A(0);
    asm volatile("cp.async.wait_group 0;" ::: "memory");
    __syncthreads();

    if (m0 + mw < Brows) {
        #pragma unroll 1
        for (int s = 0; s < NSTEP; s++) {
            // rebuild mma A fragments from row-quad data via shuffles
            uint32_t lo[4], hi[4];
            #pragma unroll
            for (int g = 0; g < 4; g++) {
                __half2 h01 = __floats2half2_rn(pf[g].x, pf[g].y);
                __half2 h23 = __floats2half2_rn(pf[g].z, pf[g].w);
                uint32_t u01 = *reinterpret_cast<uint32_t*>(&h01);
                uint32_t u23 = *reinterpret_cast<uint32_t*>(&h23);
                uint32_t s01 = __shfl_sync(0xffffffffu, u01, src0);
                uint32_t s23 = __shfl_sync(0xffffffffu, u23, src0);
                lo[g] = hi_half ? s23 : s01;
                uint32_t t01 = __shfl_sync(0xffffffffu, u01, src1);
                uint32_t t23 = __shfl_sync(0xffffffffu, u23, src1);
                hi[g] = hi_half ? t23 : t01;
            }
            if (s + 1 < NSTEP) LOAD_A(s + 1);

            const uint32_t sb = bbase + (uint32_t)s * BSTRIDE;
            uint32_t f0, f1, f2, f3;
            #pragma unroll
            for (int tp = 0; tp < 6; tp++) {
                ldsm_x4(f0, f1, f2, f3, sb + boff[tp]);
                mma16816(c0[tp * 2],     lo[0], lo[1], hi[0], hi[1], f0, f1);
                mma16816(c1[tp * 2],     lo[2], lo[3], hi[2], hi[3], f0, f1);
                mma16816(c0[tp * 2 + 1], lo[0], lo[1], hi[0], hi[1], f2, f3);
                mma16816(c1[tp * 2 + 1], lo[2], lo[3], hi[2], hi[3], f2, f3);
            }
            ldsm_x2(f0, f1, sb + bxoff);
            mma16816(c0[12], lo[0], lo[1], hi[0], hi[1], f0, f1);
            mma16816(c1[12], lo[2], lo[3], hi[2], hi[3], f0, f1);
        }

        // ---- epilogue: 4 rows per thread-quad position
        float pr0[10], pr1[10], pr2[10], pr3[10];
        #pragma unroll
        for (int j = 0; j < 10; j++) { pr0[j] = 0.f; pr1[j] = 0.f; pr2[j] = 0.f; pr3[j] = 0.f; }

        #pragma unroll
        for (int t = 0; t < 13; t++) {
            #pragma unroll
            for (int e = 0; e < 2; e++) {
                int n = t * 8 + qid * 2 + e;
                if (n < 100) {
                    float h0 = fmaxf(c0[t][0 + e] + b1s[n], 0.f);  // row qrow
                    float h1 = fmaxf(c0[t][2 + e] + b1s[n], 0.f);  // row qrow+8
                    float h2 = fmaxf(c1[t][0 + e] + b1s[n], 0.f);  // row qrow+16
                    float h3 = fmaxf(c1[t][2 + e] + b1s[n], 0.f);  // row qrow+24
                    #pragma unroll
                    for (int j = 0; j < 10; j++) {
                        pr0[j] = fmaf(h0, w2s[n][j], pr0[j]);
                        pr1[j] = fmaf(h1, w2s[n][j], pr1[j]);
                        pr2[j] = fmaf(h2, w2s[n][j], pr2[j]);
                        pr3[j] = fmaf(h3, w2s[n][j], pr3[j]);
                    }
                }
            }
        }
        #pragma unroll
        for (int mask = 2; mask >= 1; mask >>= 1) {
            #pragma unroll
            for (int j = 0; j < 10; j++) {
                pr0[j] += __shfl_xor_sync(0xffffffffu, pr0[j], mask);
                pr1[j] += __shfl_xor_sync(0xffffffffu, pr1[j], mask);
                pr2[j] += __shfl_xor_sync(0xffffffffu, pr2[j], mask);
                pr3[j] += __shfl_xor_sync(0xffffffffu, pr3[j], mask);
            }
        }
        if (qid == 0) {
            int r = m0 + mw + qrow;
            if (r < Brows) {
                #pragma unroll
                for (int j = 0; j < 10; j++) out[(size_t)r * 10 + j] = pr0[j] + b2v[j];
            }
            if (r + 8 < Brows) {
                #pragma unroll
                for (int j = 0; j < 10; j++) out[(size_t)(r + 8) * 10 + j] = pr1[j] + b2v[j];
            }
            if (r + 16 < Brows) {
                #pragma unroll
                for (int j = 0; j < 10; j++) out[(size_t)(r + 16) * 10 + j] = pr2[j] + b2v[j];
            }
            if (r + 24 < Brows) {
                #pragma unroll
                for (int j = 0; j < 10; j++) out[(size_t)(r + 24) * 10 + j] = pr3[j] + b2v[j];
            }
        }
    }
    #undef LOAD_A
}

// ---------------- launch ---------------------------------------------------

extern "C" void kernel_launch(void* const* d_in, const int* in_sizes, int n_in,
                              void* d_out, int out_size) {
    const float* x      = (const float*)d_in[0];
    const float* conv_w = (const float*)d_in[1];
    const float* fc1_w  = (const float*)d_in[2];
    const float* fc1_b  = (const float*)d_in[3];
    const float* fc2_w  = (const float*)d_in[4];
    const float* fc2_b  = (const float*)d_in[5];
    float* out = (float*)d_out;

    int Brows = in_sizes[0] / KW;

    build_w1<<<(104 * KW + 255) / 256, 256>>>(conv_w, fc1_w);

    cudaFuncSetAttribute(fused_gemm, cudaFuncAttributeMaxDynamicSharedMemorySize,
                         BSMEM);

    int rows_per_cta = 14 * ROWS_W;      // 448
    int grid = (Brows + rows_per_cta - 1) / rows_per_cta;   // 147 for 65536
    fused_gemm<<<grid, CTA_T, BSMEM>>>(x, fc1_b, fc2_w, fc2_b, out, Brows);
}

// round 10
// speedup vs baseline: 1.0663x; 1.0663x over previous
#include <cuda_runtime.h>
#include <cuda_fp16.h>
#include <cstdint>

// ---------------------------------------------------------------------------
// out = relu(x·W1effᵀ + b1)·fc2ᵀ + b2   via mma.sync m16n8k16 (fp16 in, fp32 acc)
// B (104x784 fp16, 163KB) resident in smem for whole kernel (staged once).
// A: LDG.128 row-quads -> shuffle rebuild to mma fragments (proven in R9).
// 32 rows/warp (amortizes B ldmatrix over 26 MMAs), 384 thr = 12 warps
// (170-reg cap -> no spills), persistent grid=148, warp-level chunk spread:
// round 1: warp gw does chunk gw; round 2: every 6th warp takes one of the
// 272 leftover chunks (spread across all SMs -> no second full wave).
// ---------------------------------------------------------------------------

#define KW      784
#define NSTEP   49                 // 784 / 16
#define BSTRIDE 3328               // 104 n-rows * 32 B per k-step
#define BSMEM   (NSTEP * BSTRIDE)  // 163072 B
#define CTA_T   384
#define ROWS_W  32

__device__ __half g_w1[104 * KW];

// ---------------- weight fold + fp16 conversion ----------------------------

__global__ void build_w1(const float* __restrict__ conv_w,
                         const float* __restrict__ fc1_w) {
    int idx = blockIdx.x * blockDim.x + threadIdx.x;
    if (idx >= 104 * KW) return;
    int n = idx / KW;
    int k = idx % KW;
    float v = 0.f;
    if (n < 100) {
        int y  = k / 28;
        int xx = k % 28;
        #pragma unroll
        for (int i = 0; i < 3; i++) {
            int r = y - i;
            if (r < 0 || r > 25) continue;
            #pragma unroll
            for (int j = 0; j < 3; j++) {
                int c = xx - j;
                if (c < 0 || c > 25) continue;
                v += fc1_w[n * 676 + r * 26 + c] * conv_w[i * 3 + j];
            }
        }
    }
    g_w1[n * KW + k] = __float2half(v);
}

// ---------------- PTX helpers ----------------------------------------------

__device__ __forceinline__ uint32_t smem_u32(const void* p) {
    uint32_t a;
    asm("{ .reg .u64 t; cvta.to.shared.u64 t, %1; cvt.u32.u64 %0, t; }"
        : "=r"(a) : "l"(p));
    return a;
}

__device__ __forceinline__ void ldsm_x4(uint32_t& r0, uint32_t& r1,
                                        uint32_t& r2, uint32_t& r3, uint32_t addr) {
    asm volatile("ldmatrix.sync.aligned.m8n8.x4.shared.b16 {%0,%1,%2,%3}, [%4];"
        : "=r"(r0), "=r"(r1), "=r"(r2), "=r"(r3) : "r"(addr));
}

__device__ __forceinline__ void ldsm_x2(uint32_t& r0, uint32_t& r1, uint32_t addr) {
    asm volatile("ldmatrix.sync.aligned.m8n8.x2.shared.b16 {%0,%1}, [%2];"
        : "=r"(r0), "=r"(r1) : "r"(addr));
}

__device__ __forceinline__ void mma16816(float* c,
                                         uint32_t a0, uint32_t a1, uint32_t a2, uint32_t a3,
                                         uint32_t b0, uint32_t b1) {
    asm volatile(
        "mma.sync.aligned.m16n8k16.row.col.f32.f16.f16.f32 "
        "{%0,%1,%2,%3}, {%4,%5,%6,%7}, {%8,%9}, {%0,%1,%2,%3};"
        : "+f"(c[0]), "+f"(c[1]), "+f"(c[2]), "+f"(c[3])
        : "r"(a0), "r"(a1), "r"(a2), "r"(a3), "r"(b0), "r"(b1));
}

// ---------------- fused GEMM + epilogue ------------------------------------

__global__ __launch_bounds__(CTA_T, 1)
void fused_gemm(const float* __restrict__ x,
                const float* __restrict__ fc1_b,
                const float* __restrict__ fc2_w,
                const float* __restrict__ fc2_b,
                float* __restrict__ out, int Brows) {
    extern __shared__ __align__(128) uint8_t dynsmem[];   // B: 163072 B
    __shared__ float b1s[128];
    __shared__ float w2s[100][12];
    __shared__ float b2v[16];

    const int tid = threadIdx.x;
    const int wid = tid >> 5;            // 0..11
    const int lid = tid & 31;
    const int qid = lid & 3;
    const int qrow = lid >> 2;           // 0..7

    const uint32_t bbase = smem_u32(dynsmem);

    // ---- stage B once: g_w1[n][k] -> [step s][n][2x16B], swizzled
    for (int idx = tid; idx < NSTEP * 104 * 2; idx += CTA_T) {
        int cch = idx & 1;
        int n = (idx >> 1) % 104;
        int s = (idx >> 1) / 104;
        uint32_t dst = bbase + (uint32_t)(s * 104 + n) * 32
                     + ((cch ^ ((n >> 2) & 1)) << 4);
        const __half* src = &g_w1[n * KW + s * 16 + cch * 8];
        asm volatile("cp.async.cg.shared.global [%0], [%1], 16;"
                     :: "r"(dst), "l"(src) : "memory");
    }
    asm volatile("cp.async.commit_group;" ::: "memory");

    if (tid < 128) b1s[tid] = (tid < 100) ? fc1_b[tid] : 0.f;
    if (tid < 100) {
        #pragma unroll
        for (int j = 0; j < 10; j++) w2s[tid][j] = fc2_w[j * 100 + tid];
    }
    if (tid < 10) b2v[tid] = fc2_b[tid];

    // ---- B ldmatrix lane offsets (constant per thread)
    const int b_nl = ((lid >> 4) & 1) * 8 + (lid & 7);
    const int b_ko = (lid >> 3) & 1;
    uint32_t boff[6];
    #pragma unroll
    for (int tp = 0; tp < 6; tp++) {
        int n_l = tp * 16 + b_nl;
        boff[tp] = (uint32_t)(n_l * 32 + ((b_ko ^ ((n_l >> 2) & 1)) << 4));
    }
    const int nx = 96 + (lid & 7);
    const uint32_t bxoff = (uint32_t)(nx * 32 + ((b_ko ^ ((nx >> 2) & 1)) << 4));

    // shuffle sources for A fragment rebuild (proven in R9)
    const int src0 = (lid & 28) | (qid >> 1);
    const int src1 = src0 + 2;
    const bool hi_half = (qid & 1);

    asm volatile("cp.async.wait_group 0;" ::: "memory");
    __syncthreads();
    // no barriers below this point — warps fully independent

    // ---- chunk schedule: 32-row chunks
    const int nck   = (Brows + ROWS_W - 1) / ROWS_W;       // 2048
    const int nwarp = gridDim.x * (CTA_T >> 5);            // 1776
    const int gw    = blockIdx.x * (CTA_T >> 5) + wid;

    int mych[4];
    int nmy = 0;
    if (gw < nck) mych[nmy++] = gw;
    int rem = nck - nwarp;
    if (rem > 0) {
        if (rem <= nwarp) {
            int stride = nwarp / rem;                      // 6 for 65536 rows
            if ((gw % stride) == 0 && (gw / stride) < rem)
                mych[nmy++] = nwarp + gw / stride;
        } else {
            for (int c = nwarp + gw; c < nck && nmy < 4; c += nwarp)
                mych[nmy++] = c;
        }
    }

    for (int ci = 0; ci < nmy; ci++) {
        const int mbase = mych[ci] * ROWS_W;

        // A geometry: LDG row-quads. Group g: row = mbase + 8g + (lid>>2),
        // lane holds k = s*16 + (lid&3)*4 .. +3 (float4).
        const int rowb = mbase + (lid >> 2);
        const float* xb = x + (size_t)rowb * KW + (lid & 3) * 4;
        bool pg[4];
        #pragma unroll
        for (int g = 0; g < 4; g++) pg[g] = (rowb + 8 * g) < Brows;

        float c0[13][4], c1[13][4];
        #pragma unroll
        for (int t = 0; t < 13; t++)
            #pragma unroll
            for (int q = 0; q < 4; q++) { c0[t][q] = 0.f; c1[t][q] = 0.f; }

        float4 pf[4];

        #define LOAD_A(s) do {                                                \
            const float4 z4 = make_float4(0.f, 0.f, 0.f, 0.f);                \
            pf[0] = pg[0] ? *reinterpret_cast<const float4*>(xb + (s) * 16)           : z4; \
            pf[1] = pg[1] ? *reinterpret_cast<const float4*>(xb + 8 * KW + (s) * 16)  : z4; \
            pf[2] = pg[2] ? *reinterpret_cast<const float4*>(xb + 16 * KW + (s) * 16) : z4; \
            pf[3] = pg[3] ? *reinterpret_cast<const float4*>(xb + 24 * KW + (s) * 16) : z4; \
        } while (0)

        LOAD_A(0);

        #pragma unroll 1
        for (int s = 0; s < NSTEP; s++) {
            // rebuild mma A fragments from row-quad data via shuffles
            uint32_t lo[4], hi[4];
            #pragma unroll
            for (int g = 0; g < 4; g++) {
                __half2 h01 = __floats2half2_rn(pf[g].x, pf[g].y);
                __half2 h23 = __floats2half2_rn(pf[g].z, pf[g].w);
                uint32_t u01 = *reinterpret_cast<uint32_t*>(&h01);
                uint32_t u23 = *reinterpret_cast<uint32_t*>(&h23);
                uint32_t s01 = __shfl_sync(0xffffffffu, u01, src0);
                uint32_t s23 = __shfl_sync(0xffffffffu, u23, src0);
                lo[g] = hi_half ? s23 : s01;
                uint32_t t01 = __shfl_sync(0xffffffffu, u01, src1);
                uint32_t t23 = __shfl_sync(0xffffffffu, u23, src1);
                hi[g] = hi_half ? t23 : t01;
            }
            if (s + 1 < NSTEP) LOAD_A(s + 1);

            const uint32_t sb = bbase + (uint32_t)s * BSTRIDE;
            uint32_t f0, f1, f2, f3;
            #pragma unroll
            for (int tp = 0; tp < 6; tp++) {
                ldsm_x4(f0, f1, f2, f3, sb + boff[tp]);
                mma16816(c0[tp * 2],     lo[0], lo[1], hi[0], hi[1], f0, f1);
                mma16816(c1[tp * 2],     lo[2], lo[3], hi[2], hi[3], f0, f1);
                mma16816(c0[tp * 2 + 1], lo[0], lo[1], hi[0], hi[1], f2, f3);
                mma16816(c1[tp * 2 + 1], lo[2], lo[3], hi[2], hi[3], f2, f3);
            }
            ldsm_x2(f0, f1, sb + bxoff);
            mma16816(c0[12], lo[0], lo[1], hi[0], hi[1], f0, f1);
            mma16816(c1[12], lo[2], lo[3], hi[2], hi[3], f0, f1);
        }
        #undef LOAD_A

        // ---- epilogue: 4 rows per thread-quad position
        float pr0[10], pr1[10], pr2[10], pr3[10];
        #pragma unroll
        for (int j = 0; j < 10; j++) { pr0[j] = 0.f; pr1[j] = 0.f; pr2[j] = 0.f; pr3[j] = 0.f; }

        #pragma unroll
        for (int t = 0; t < 13; t++) {
            #pragma unroll
            for (int e = 0; e < 2; e++) {
                int n = t * 8 + qid * 2 + e;
                if (n < 100) {
                    float h0 = fmaxf(c0[t][0 + e] + b1s[n], 0.f);  // row qrow
                    float h1 = fmaxf(c0[t][2 + e] + b1s[n], 0.f);  // row qrow+8
                    float h2 = fmaxf(c1[t][0 + e] + b1s[n], 0.f);  // row qrow+16
                    float h3 = fmaxf(c1[t][2 + e] + b1s[n], 0.f);  // row qrow+24
                    #pragma unroll
                    for (int j = 0; j < 10; j++) {
                        pr0[j] = fmaf(h0, w2s[n][j], pr0[j]);
                        pr1[j] = fmaf(h1, w2s[n][j], pr1[j]);
                        pr2[j] = fmaf(h2, w2s[n][j], pr2[j]);
                        pr3[j] = fmaf(h3, w2s[n][j], pr3[j]);
                    }
                }
            }
        }
        #pragma unroll
        for (int mask = 2; mask >= 1; mask >>= 1) {
            #pragma unroll
            for (int j = 0; j < 10; j++) {
                pr0[j] += __shfl_xor_sync(0xffffffffu, pr0[j], mask);
                pr1[j] += __shfl_xor_sync(0xffffffffu, pr1[j], mask);
                pr2[j] += __shfl_xor_sync(0xffffffffu, pr2[j], mask);
                pr3[j] += __shfl_xor_sync(0xffffffffu, pr3[j], mask);
            }
        }
        if (qid == 0) {
            int r = mbase + qrow;
            if (r < Brows) {
                #pragma unroll
                for (int j = 0; j < 10; j++) out[(size_t)r * 10 + j] = pr0[j] + b2v[j];
            }
            if (r + 8 < Brows) {
                #pragma unroll
                for (int j = 0; j < 10; j++) out[(size_t)(r + 8) * 10 + j] = pr1[j] + b2v[j];
            }
            if (r + 16 < Brows) {
                #pragma unroll
                for (int j = 0; j < 10; j++) out[(size_t)(r + 16) * 10 + j] = pr2[j] + b2v[j];
            }
            if (r + 24 < Brows) {
                #pragma unroll
                for (int j = 0; j < 10; j++) out[(size_t)(r + 24) * 10 + j] = pr3[j] + b2v[j];
            }
        }
    }
}

// ---------------- launch ---------------------------------------------------

extern "C" void kernel_launch(void* const* d_in, const int* in_sizes, int n_in,
                              void* d_out, int out_size) {
    const float* x      = (const float*)d_in[0];
    const float* conv_w = (const float*)d_in[1];
    const float* fc1_w  = (const float*)d_in[2];
    const float* fc1_b  = (const float*)d_in[3];
    const float* fc2_w  = (const float*)d_in[4];
    const float* fc2_b  = (const float*)d_in[5];
    float* out = (float*)d_out;

    int Brows = in_sizes[0] / KW;

    build_w1<<<(104 * KW + 255) / 256, 256>>>(conv_w, fc1_w);

    cudaFuncSetAttribute(fused_gemm, cudaFuncAttributeMaxDynamicSharedMemorySize,
                         BSMEM);

    fused_gemm<<<148, CTA_T, BSMEM>>>(x, fc1_b, fc2_w, fc2_b, out, Brows);
}

// round 11
// speedup vs baseline: 1.4300x; 1.3411x over previous
#include <cuda_runtime.h>
#include <cuda_fp16.h>
#include <cstdint>

// ---------------------------------------------------------------------------
// out = relu(x·W1effᵀ + b1)·fc2ᵀ + b2   via mma.sync m16n8k16 (fp16 in, fp32 acc)
// B (104x784 fp16, 163KB) resident in smem for whole kernel (staged once).
// A: LDG.128 row-quads -> shuffle rebuild into mma fragments (proven R9/R10).
// 16 rows/warp (R8 operating point: 124 regs -> 16 warps/SM), 512 threads,
// persistent grid=148, barrier-free warp-level grid-stride over 16-row chunks
// (spreads the partial second round across ALL SMs; no idle-SM wave).
// ---------------------------------------------------------------------------

#define KW      784
#define NSTEP   49                 // 784 / 16
#define BSTRIDE 3328               // 104 n-rows * 32 B per k-step
#define BSMEM   (NSTEP * BSTRIDE)  // 163072 B
#define CTA_T   512
#define ROWS_W  16

__device__ __half g_w1[104 * KW];

// ---------------- weight fold + fp16 conversion ----------------------------

__global__ void build_w1(const float* __restrict__ conv_w,
                         const float* __restrict__ fc1_w) {
    int idx = blockIdx.x * blockDim.x + threadIdx.x;
    if (idx >= 104 * KW) return;
    int n = idx / KW;
    int k = idx % KW;
    float v = 0.f;
    if (n < 100) {
        int y  = k / 28;
        int xx = k % 28;
        #pragma unroll
        for (int i = 0; i < 3; i++) {
            int r = y - i;
            if (r < 0 || r > 25) continue;
            #pragma unroll
            for (int j = 0; j < 3; j++) {
                int c = xx - j;
                if (c < 0 || c > 25) continue;
                v += fc1_w[n * 676 + r * 26 + c] * conv_w[i * 3 + j];
            }
        }
    }
    g_w1[n * KW + k] = __float2half(v);
}

// ---------------- PTX helpers ----------------------------------------------

__device__ __forceinline__ uint32_t smem_u32(const void* p) {
    uint32_t a;
    asm("{ .reg .u64 t; cvta.to.shared.u64 t, %1; cvt.u32.u64 %0, t; }"
        : "=r"(a) : "l"(p));
    return a;
}

__device__ __forceinline__ void ldsm_x4(uint32_t& r0, uint32_t& r1,
                                        uint32_t& r2, uint32_t& r3, uint32_t addr) {
    asm volatile("ldmatrix.sync.aligned.m8n8.x4.shared.b16 {%0,%1,%2,%3}, [%4];"
        : "=r"(r0), "=r"(r1), "=r"(r2), "=r"(r3) : "r"(addr));
}

__device__ __forceinline__ void ldsm_x2(uint32_t& r0, uint32_t& r1, uint32_t addr) {
    asm volatile("ldmatrix.sync.aligned.m8n8.x2.shared.b16 {%0,%1}, [%2];"
        : "=r"(r0), "=r"(r1) : "r"(addr));
}

__device__ __forceinline__ void mma16816(float* c,
                                         uint32_t a0, uint32_t a1, uint32_t a2, uint32_t a3,
                                         uint32_t b0, uint32_t b1) {
    asm volatile(
        "mma.sync.aligned.m16n8k16.row.col.f32.f16.f16.f32 "
        "{%0,%1,%2,%3}, {%4,%5,%6,%7}, {%8,%9}, {%0,%1,%2,%3};"
        : "+f"(c[0]), "+f"(c[1]), "+f"(c[2]), "+f"(c[3])
        : "r"(a0), "r"(a1), "r"(a2), "r"(a3), "r"(b0), "r"(b1));
}

// ---------------- fused GEMM + epilogue ------------------------------------

__global__ __launch_bounds__(CTA_T, 1)
void fused_gemm(const float* __restrict__ x,
                const float* __restrict__ fc1_b,
                const float* __restrict__ fc2_w,
                const float* __restrict__ fc2_b,
                float* __restrict__ out, int Brows) {
    extern __shared__ __align__(128) uint8_t dynsmem[];   // B: 163072 B
    __shared__ float b1s[128];
    __shared__ float w2s[100][12];
    __shared__ float b2v[16];

    const int tid = threadIdx.x;
    const int wid = tid >> 5;            // 0..15
    const int lid = tid & 31;
    const int qid = lid & 3;
    const int qrow = lid >> 2;           // 0..7

    const uint32_t bbase = smem_u32(dynsmem);

    // ---- stage B once: g_w1[n][k] -> [step s][n][2x16B], swizzled
    for (int idx = tid; idx < NSTEP * 104 * 2; idx += CTA_T) {
        int cch = idx & 1;
        int n = (idx >> 1) % 104;
        int s = (idx >> 1) / 104;
        uint32_t dst = bbase + (uint32_t)(s * 104 + n) * 32
                     + ((cch ^ ((n >> 2) & 1)) << 4);
        const __half* src = &g_w1[n * KW + s * 16 + cch * 8];
        asm volatile("cp.async.cg.shared.global [%0], [%1], 16;"
                     :: "r"(dst), "l"(src) : "memory");
    }
    asm volatile("cp.async.commit_group;" ::: "memory");

    if (tid < 128) b1s[tid] = (tid < 100) ? fc1_b[tid] : 0.f;
    if (tid < 100) {
        #pragma unroll
        for (int j = 0; j < 10; j++) w2s[tid][j] = fc2_w[j * 100 + tid];
    }
    if (tid < 10) b2v[tid] = fc2_b[tid];

    // ---- B ldmatrix lane offsets (constant per thread)
    const int b_nl = ((lid >> 4) & 1) * 8 + (lid & 7);
    const int b_ko = (lid >> 3) & 1;
    uint32_t boff[6];
    #pragma unroll
    for (int tp = 0; tp < 6; tp++) {
        int n_l = tp * 16 + b_nl;
        boff[tp] = (uint32_t)(n_l * 32 + ((b_ko ^ ((n_l >> 2) & 1)) << 4));
    }
    const int nx = 96 + (lid & 7);
    const uint32_t bxoff = (uint32_t)(nx * 32 + ((b_ko ^ ((nx >> 2) & 1)) << 4));

    // shuffle sources for A fragment rebuild (proven R9/R10)
    const int src0 = (lid & 28) | (qid >> 1);
    const int src1 = src0 + 2;
    const bool hi_half = (qid & 1);

    asm volatile("cp.async.wait_group 0;" ::: "memory");
    __syncthreads();
    // no barriers below this point — warps fully independent

    // ---- warp-persistent grid-stride over 16-row chunks
    const int nck   = (Brows + ROWS_W - 1) / ROWS_W;       // 4096
    const int nwarp = gridDim.x * (CTA_T >> 5);            // 2368
    const int gw    = blockIdx.x * (CTA_T >> 5) + wid;

    for (int ck = gw; ck < nck; ck += nwarp) {
        const int mbase = ck * ROWS_W;

        // A geometry: LDG.128 row-quads. Group g (0,1): row = mbase+8g+(lid>>2),
        // lane holds k = s*16 + (lid&3)*4 .. +3 (float4).
        const int rowb = mbase + (lid >> 2);
        const float* xb = x + (size_t)rowb * KW + (lid & 3) * 4;
        const bool pg0 = rowb < Brows;
        const bool pg1 = (rowb + 8) < Brows;

        float c[13][4];
        #pragma unroll
        for (int t = 0; t < 13; t++)
            #pragma unroll
            for (int q = 0; q < 4; q++) c[t][q] = 0.f;

        float4 pfa[2], pfb[2];

        #define LOAD_A(s, pf) do {                                            \
            const float4 z4 = make_float4(0.f, 0.f, 0.f, 0.f);                \
            (pf)[0] = pg0 ? *reinterpret_cast<const float4*>(xb + (s) * 16)          : z4; \
            (pf)[1] = pg1 ? *reinterpret_cast<const float4*>(xb + 8 * KW + (s) * 16) : z4; \
        } while (0)

        #define STEP(s, pf) do {                                              \
            uint32_t lo[2], hi[2];                                            \
            _Pragma("unroll")                                                 \
            for (int g = 0; g < 2; g++) {                                     \
                __half2 h01 = __floats2half2_rn((pf)[g].x, (pf)[g].y);        \
                __half2 h23 = __floats2half2_rn((pf)[g].z, (pf)[g].w);        \
                uint32_t u01 = *reinterpret_cast<uint32_t*>(&h01);            \
                uint32_t u23 = *reinterpret_cast<uint32_t*>(&h23);            \
                uint32_t s01 = __shfl_sync(0xffffffffu, u01, src0);           \
                uint32_t s23 = __shfl_sync(0xffffffffu, u23, src0);           \
                lo[g] = hi_half ? s23 : s01;                                  \
                uint32_t t01 = __shfl_sync(0xffffffffu, u01, src1);           \
                uint32_t t23 = __shfl_sync(0xffffffffu, u23, src1);           \
                hi[g] = hi_half ? t23 : t01;                                  \
            }                                                                 \
            const uint32_t sb = bbase + (uint32_t)(s) * BSTRIDE;              \
            uint32_t f0, f1, f2, f3;                                          \
            _Pragma("unroll")                                                 \
            for (int tp = 0; tp < 6; tp++) {                                  \
                ldsm_x4(f0, f1, f2, f3, sb + boff[tp]);                       \
                mma16816(c[tp * 2],     lo[0], lo[1], hi[0], hi[1], f0, f1);  \
                mma16816(c[tp * 2 + 1], lo[0], lo[1], hi[0], hi[1], f2, f3);  \
            }                                                                 \
            ldsm_x2(f0, f1, sb + bxoff);                                      \
            mma16816(c[12], lo[0], lo[1], hi[0], hi[1], f0, f1);              \
        } while (0)

        LOAD_A(0, pfa);
        LOAD_A(1, pfb);

        #pragma unroll 1
        for (int s = 0; s < 48; s += 2) {
            STEP(s, pfa);
            if (s + 2 < NSTEP) LOAD_A(s + 2, pfa);
            STEP(s + 1, pfb);
            if (s + 3 < NSTEP) LOAD_A(s + 3, pfb);
        }
        STEP(48, pfa);

        #undef LOAD_A
        #undef STEP

        // ---- epilogue: h = relu(c + b1); p = h·fc2ᵀ; quad-reduce; + b2
        float p0[10], p1[10];
        #pragma unroll
        for (int j = 0; j < 10; j++) { p0[j] = 0.f; p1[j] = 0.f; }

        #pragma unroll
        for (int t = 0; t < 13; t++) {
            #pragma unroll
            for (int e = 0; e < 2; e++) {
                int n = t * 8 + qid * 2 + e;
                if (n < 100) {
                    float h0 = fmaxf(c[t][0 + e] + b1s[n], 0.f);  // row qrow
                    float h1 = fmaxf(c[t][2 + e] + b1s[n], 0.f);  // row qrow+8
                    #pragma unroll
                    for (int j = 0; j < 10; j++) {
                        p0[j] = fmaf(h0, w2s[n][j], p0[j]);
                        p1[j] = fmaf(h1, w2s[n][j], p1[j]);
                    }
                }
            }
        }
        #pragma unroll
        for (int mask = 2; mask >= 1; mask >>= 1) {
            #pragma unroll
            for (int j = 0; j < 10; j++) {
                p0[j] += __shfl_xor_sync(0xffffffffu, p0[j], mask);
                p1[j] += __shfl_xor_sync(0xffffffffu, p1[j], mask);
            }
        }
        if (qid == 0) {
            int r0 = mbase + qrow;
            int r1 = r0 + 8;
            if (r0 < Brows) {
                #pragma unroll
                for (int j = 0; j < 10; j++)
                    out[(size_t)r0 * 10 + j] = p0[j] + b2v[j];
            }
            if (r1 < Brows) {
                #pragma unroll
                for (int j = 0; j < 10; j++)
                    out[(size_t)r1 * 10 + j] = p1[j] + b2v[j];
            }
        }
    }
}

// ---------------- launch ---------------------------------------------------

extern "C" void kernel_launch(void* const* d_in, const int* in_sizes, int n_in,
                              void* d_out, int out_size) {
    const float* x      = (const float*)d_in[0];
    const float* conv_w = (const float*)d_in[1];
    const float* fc1_w  = (const float*)d_in[2];
    const float* fc1_b  = (const float*)d_in[3];
    const float* fc2_w  = (const float*)d_in[4];
    const float* fc2_b  = (const float*)d_in[5];
    float* out = (float*)d_out;

    int Brows = in_sizes[0] / KW;

    build_w1<<<(104 * KW + 255) / 256, 256>>>(conv_w, fc1_w);

    cudaFuncSetAttribute(fused_gemm, cudaFuncAttributeMaxDynamicSharedMemorySize,
                         BSMEM);

    fused_gemm<<<148, CTA_T, BSMEM>>>(x, fc1_b, fc2_w, fc2_b, out, Brows);
}

// round 12
// speedup vs baseline: 1.4990x; 1.0483x over previous
#include <cuda_runtime.h>
#include <cuda_fp16.h>
#include <cstdint>

// ---------------------------------------------------------------------------
// out = relu(x·W1effᵀ + b1)·fc2ᵀ + b2   via mma.sync m16n8k16 (fp16 in, fp32 acc)
// B (104x784 fp16, 163KB) resident in smem (staged once per CTA).
// A: LDG.128 row-quads -> shuffle rebuild (proven R9-R11).
// MANUALLY SOFTWARE-PIPELINED: B fragments double-buffered across k-steps,
// next step's 7 LDSMs interleaved between current step's 13 MMAs (asm order
// is SASS order). 448 thr = 14 warps @ 146-reg cap -> no spills, headroom.
// Persistent grid=148; 2072 warps over 4096 chunks = exactly 2 chunks/warp.
// ---------------------------------------------------------------------------

#define KW      784
#define NSTEP   49                 // 784 / 16
#define BSTRIDE 3328               // 104 n-rows * 32 B per k-step
#define BSMEM   (NSTEP * BSTRIDE)  // 163072 B
#define CTA_T   448
#define ROWS_W  16

__device__ __half g_w1[104 * KW];

// ---------------- weight fold + fp16 conversion ----------------------------

__global__ void build_w1(const float* __restrict__ conv_w,
                         const float* __restrict__ fc1_w) {
    int idx = blockIdx.x * blockDim.x + threadIdx.x;
    if (idx >= 104 * KW) return;
    int n = idx / KW;
    int k = idx % KW;
    float v = 0.f;
    if (n < 100) {
        int y  = k / 28;
        int xx = k % 28;
        #pragma unroll
        for (int i = 0; i < 3; i++) {
            int r = y - i;
            if (r < 0 || r > 25) continue;
            #pragma unroll
            for (int j = 0; j < 3; j++) {
                int c = xx - j;
                if (c < 0 || c > 25) continue;
                v += fc1_w[n * 676 + r * 26 + c] * conv_w[i * 3 + j];
            }
        }
    }
    g_w1[n * KW + k] = __float2half(v);
}

// ---------------- PTX helpers ----------------------------------------------

__device__ __forceinline__ uint32_t smem_u32(const void* p) {
    uint32_t a;
    asm("{ .reg .u64 t; cvta.to.shared.u64 t, %1; cvt.u32.u64 %0, t; }"
        : "=r"(a) : "l"(p));
    return a;
}

__device__ __forceinline__ void ldsm_x4(uint32_t& r0, uint32_t& r1,
                                        uint32_t& r2, uint32_t& r3, uint32_t addr) {
    asm volatile("ldmatrix.sync.aligned.m8n8.x4.shared.b16 {%0,%1,%2,%3}, [%4];"
        : "=r"(r0), "=r"(r1), "=r"(r2), "=r"(r3) : "r"(addr));
}

__device__ __forceinline__ void ldsm_x2(uint32_t& r0, uint32_t& r1, uint32_t addr) {
    asm volatile("ldmatrix.sync.aligned.m8n8.x2.shared.b16 {%0,%1}, [%2];"
        : "=r"(r0), "=r"(r1) : "r"(addr));
}

__device__ __forceinline__ void mma16816(float* c,
                                         uint32_t a0, uint32_t a1, uint32_t a2, uint32_t a3,
                                         uint32_t b0, uint32_t b1) {
    asm volatile(
        "mma.sync.aligned.m16n8k16.row.col.f32.f16.f16.f32 "
        "{%0,%1,%2,%3}, {%4,%5,%6,%7}, {%8,%9}, {%0,%1,%2,%3};"
        : "+f"(c[0]), "+f"(c[1]), "+f"(c[2]), "+f"(c[3])
        : "r"(a0), "r"(a1), "r"(a2), "r"(a3), "r"(b0), "r"(b1));
}

// ---------------- fused GEMM + epilogue ------------------------------------

__global__ __launch_bounds__(CTA_T, 1)
void fused_gemm(const float* __restrict__ x,
                const float* __restrict__ fc1_b,
                const float* __restrict__ fc2_w,
                const float* __restrict__ fc2_b,
                float* __restrict__ out, int Brows) {
    extern __shared__ __align__(128) uint8_t dynsmem[];   // B: 163072 B
    __shared__ float b1s[128];
    __shared__ float w2s[100][12];
    __shared__ float b2v[16];

    const int tid = threadIdx.x;
    const int wid = tid >> 5;            // 0..13
    const int lid = tid & 31;
    const int qid = lid & 3;
    const int qrow = lid >> 2;           // 0..7

    const uint32_t bbase = smem_u32(dynsmem);

    // ---- stage B once: g_w1[n][k] -> [step s][n][2x16B], swizzled
    for (int idx = tid; idx < NSTEP * 104 * 2; idx += CTA_T) {
        int cch = idx & 1;
        int n = (idx >> 1) % 104;
        int s = (idx >> 1) / 104;
        uint32_t dst = bbase + (uint32_t)(s * 104 + n) * 32
                     + ((cch ^ ((n >> 2) & 1)) << 4);
        const __half* src = &g_w1[n * KW + s * 16 + cch * 8];
        asm volatile("cp.async.cg.shared.global [%0], [%1], 16;"
                     :: "r"(dst), "l"(src) : "memory");
    }
    asm volatile("cp.async.commit_group;" ::: "memory");

    if (tid < 128) b1s[tid] = (tid < 100) ? fc1_b[tid] : 0.f;
    if (tid < 100) {
        #pragma unroll
        for (int j = 0; j < 10; j++) w2s[tid][j] = fc2_w[j * 100 + tid];
    }
    if (tid < 10) b2v[tid] = fc2_b[tid];

    // ---- B ldmatrix lane offsets (constant per thread)
    const int b_nl = ((lid >> 4) & 1) * 8 + (lid & 7);
    const int b_ko = (lid >> 3) & 1;
    uint32_t boff[6];
    #pragma unroll
    for (int tp = 0; tp < 6; tp++) {
        int n_l = tp * 16 + b_nl;
        boff[tp] = (uint32_t)(n_l * 32 + ((b_ko ^ ((n_l >> 2) & 1)) << 4));
    }
    const int nx = 96 + (lid & 7);
    const uint32_t bxoff = (uint32_t)(nx * 32 + ((b_ko ^ ((nx >> 2) & 1)) << 4));

    // shuffle sources for A fragment rebuild (proven R9-R11)
    const int src0 = (lid & 28) | (qid >> 1);
    const int src1 = src0 + 2;
    const bool hi_half = (qid & 1);

    asm volatile("cp.async.wait_group 0;" ::: "memory");
    __syncthreads();
    // no barriers below this point — warps fully independent

    const int nck   = (Brows + ROWS_W - 1) / ROWS_W;       // 4096
    const int nwarp = gridDim.x * (CTA_T >> 5);            // 2072
    const int gw    = blockIdx.x * (CTA_T >> 5) + wid;

    for (int ck = gw; ck < nck; ck += nwarp) {
        const int mbase = ck * ROWS_W;

        const int rowb = mbase + (lid >> 2);
        const float* xb = x + (size_t)rowb * KW + (lid & 3) * 4;
        const bool pg0 = rowb < Brows;
        const bool pg1 = (rowb + 8) < Brows;

        float c[13][4];
        #pragma unroll
        for (int t = 0; t < 13; t++)
            #pragma unroll
            for (int q = 0; q < 4; q++) c[t][q] = 0.f;

        float4 pf[2];            // A raw fp32, single buffer (1-step distance)
        uint32_t bfA[26], bfB[26];  // B fragments, double-buffered

        #define LOAD_A(s) do {                                                \
            const float4 z4 = make_float4(0.f, 0.f, 0.f, 0.f);                \
            pf[0] = pg0 ? *reinterpret_cast<const float4*>(xb + (s) * 16)          : z4; \
            pf[1] = pg1 ? *reinterpret_cast<const float4*>(xb + 8 * KW + (s) * 16) : z4; \
        } while (0)

        #define LDSM_STEP(BF, s) do {                                         \
            const uint32_t sb_ = bbase + (uint32_t)(s) * BSTRIDE;             \
            ldsm_x4((BF)[0],  (BF)[1],  (BF)[2],  (BF)[3],  sb_ + boff[0]);   \
            ldsm_x4((BF)[4],  (BF)[5],  (BF)[6],  (BF)[7],  sb_ + boff[1]);   \
            ldsm_x4((BF)[8],  (BF)[9],  (BF)[10], (BF)[11], sb_ + boff[2]);   \
            ldsm_x4((BF)[12], (BF)[13], (BF)[14], (BF)[15], sb_ + boff[3]);   \
            ldsm_x4((BF)[16], (BF)[17], (BF)[18], (BF)[19], sb_ + boff[4]);   \
            ldsm_x4((BF)[20], (BF)[21], (BF)[22], (BF)[23], sb_ + boff[5]);   \
            ldsm_x2((BF)[24], (BF)[25], sb_ + bxoff);                         \
        } while (0)

        // A rebuild: pf (step s) -> a0..a3 fragments
        #define REBUILD_A() do {                                              \
            __half2 h01a = __floats2half2_rn(pf[0].x, pf[0].y);               \
            __half2 h23a = __floats2half2_rn(pf[0].z, pf[0].w);               \
            __half2 h01b = __floats2half2_rn(pf[1].x, pf[1].y);               \
            __half2 h23b = __floats2half2_rn(pf[1].z, pf[1].w);               \
            uint32_t u01a = *reinterpret_cast<uint32_t*>(&h01a);              \
            uint32_t u23a = *reinterpret_cast<uint32_t*>(&h23a);              \
            uint32_t u01b = *reinterpret_cast<uint32_t*>(&h01b);              \
            uint32_t u23b = *reinterpret_cast<uint32_t*>(&h23b);              \
            uint32_t s01 = __shfl_sync(0xffffffffu, u01a, src0);              \
            uint32_t s23 = __shfl_sync(0xffffffffu, u23a, src0);              \
            a0 = hi_half ? s23 : s01;                                         \
            uint32_t t01 = __shfl_sync(0xffffffffu, u01a, src1);              \
            uint32_t t23 = __shfl_sync(0xffffffffu, u23a, src1);              \
            a2 = hi_half ? t23 : t01;                                         \
            s01 = __shfl_sync(0xffffffffu, u01b, src0);                       \
            s23 = __shfl_sync(0xffffffffu, u23b, src0);                       \
            a1 = hi_half ? s23 : s01;                                         \
            t01 = __shfl_sync(0xffffffffu, u01b, src1);                       \
            t23 = __shfl_sync(0xffffffffu, u23b, src1);                       \
            a3 = hi_half ? t23 : t01;                                         \
        } while (0)

        // Pipelined step: MMAs use CUR (loaded last step); LDSMs fill NXT
        // with step (s+1), interleaved between MMA pairs (asm order = SASS).
        #define STEP_PIPE(s, CUR, NXT) do {                                   \
            uint32_t a0, a1, a2, a3;                                          \
            REBUILD_A();                                                      \
            LOAD_A((s) + 1);                                                  \
            const uint32_t sbn = bbase + (uint32_t)((s) + 1) * BSTRIDE;       \
            ldsm_x4((NXT)[0], (NXT)[1], (NXT)[2], (NXT)[3], sbn + boff[0]);   \
            mma16816(c[0],  a0, a1, a2, a3, (CUR)[0],  (CUR)[1]);             \
            mma16816(c[1],  a0, a1, a2, a3, (CUR)[2],  (CUR)[3]);             \
            ldsm_x4((NXT)[4], (NXT)[5], (NXT)[6], (NXT)[7], sbn + boff[1]);   \
            mma16816(c[2],  a0, a1, a2, a3, (CUR)[4],  (CUR)[5]);             \
            mma16816(c[3],  a0, a1, a2, a3, (CUR)[6],  (CUR)[7]);             \
            ldsm_x4((NXT)[8], (NXT)[9], (NXT)[10], (NXT)[11], sbn + boff[2]); \
            mma16816(c[4],  a0, a1, a2, a3, (CUR)[8],  (CUR)[9]);             \
            mma16816(c[5],  a0, a1, a2, a3, (CUR)[10], (CUR)[11]);            \
            ldsm_x4((NXT)[12], (NXT)[13], (NXT)[14], (NXT)[15], sbn + boff[3]); \
            mma16816(c[6],  a0, a1, a2, a3, (CUR)[12], (CUR)[13]);            \
            mma16816(c[7],  a0, a1, a2, a3, (CUR)[14], (CUR)[15]);            \
            ldsm_x4((NXT)[16], (NXT)[17], (NXT)[18], (NXT)[19], sbn + boff[4]); \
            mma16816(c[8],  a0, a1, a2, a3, (CUR)[16], (CUR)[17]);            \
            mma16816(c[9],  a0, a1, a2, a3, (CUR)[18], (CUR)[19]);            \
            ldsm_x4((NXT)[20], (NXT)[21], (NXT)[22], (NXT)[23], sbn + boff[5]); \
            mma16816(c[10], a0, a1, a2, a3, (CUR)[20], (CUR)[21]);            \
            mma16816(c[11], a0, a1, a2, a3, (CUR)[22], (CUR)[23]);            \
            ldsm_x2((NXT)[24], (NXT)[25], sbn + bxoff);                       \
            mma16816(c[12], a0, a1, a2, a3, (CUR)[24], (CUR)[25]);            \
        } while (0)

        #define STEP_LAST(CUR) do {                                           \
            uint32_t a0, a1, a2, a3;                                          \
            REBUILD_A();                                                      \
            mma16816(c[0],  a0, a1, a2, a3, (CUR)[0],  (CUR)[1]);             \
            mma16816(c[1],  a0, a1, a2, a3, (CUR)[2],  (CUR)[3]);             \
            mma16816(c[2],  a0, a1, a2, a3, (CUR)[4],  (CUR)[5]);             \
            mma16816(c[3],  a0, a1, a2, a3, (CUR)[6],  (CUR)[7]);             \
            mma16816(c[4],  a0, a1, a2, a3, (CUR)[8],  (CUR)[9]);             \
            mma16816(c[5],  a0, a1, a2, a3, (CUR)[10], (CUR)[11]);            \
            mma16816(c[6],  a0, a1, a2, a3, (CUR)[12], (CUR)[13]);            \
            mma16816(c[7],  a0, a1, a2, a3, (CUR)[14], (CUR)[15]);            \
            mma16816(c[8],  a0, a1, a2, a3, (CUR)[16], (CUR)[17]);            \
            mma16816(c[9],  a0, a1, a2, a3, (CUR)[18], (CUR)[19]);            \
            mma16816(c[10], a0, a1, a2, a3, (CUR)[20], (CUR)[21]);            \
            mma16816(c[11], a0, a1, a2, a3, (CUR)[22], (CUR)[23]);            \
            mma16816(c[12], a0, a1, a2, a3, (CUR)[24], (CUR)[25]);            \
        } while (0)

        // prologue: A(0) + B frags(0)
        LOAD_A(0);
        LDSM_STEP(bfA, 0);

        // 48 pipelined steps (24 double-iterations), then final step 48
        #pragma unroll 1
        for (int s = 0; s < 48; s += 2) {
            STEP_PIPE(s, bfA, bfB);
            STEP_PIPE(s + 1, bfB, bfA);
        }
        STEP_LAST(bfA);   // step 48 (frags loaded during step 47; A via LOAD_A(48))

        #undef LOAD_A
        #undef LDSM_STEP
        #undef REBUILD_A
        #undef STEP_PIPE
        #undef STEP_LAST

        // ---- epilogue: h = relu(c + b1); p = h·fc2ᵀ; quad-reduce; + b2
        float p0[10], p1[10];
        #pragma unroll
        for (int j = 0; j < 10; j++) { p0[j] = 0.f; p1[j] = 0.f; }

        #pragma unroll
        for (int t = 0; t < 13; t++) {
            #pragma unroll
            for (int e = 0; e < 2; e++) {
                int n = t * 8 + qid * 2 + e;
                if (n < 100) {
                    float h0 = fmaxf(c[t][0 + e] + b1s[n], 0.f);  // row qrow
                    float h1 = fmaxf(c[t][2 + e] + b1s[n], 0.f);  // row qrow+8
                    #pragma unroll
                    for (int j = 0; j < 10; j++) {
                        p0[j] = fmaf(h0, w2s[n][j], p0[j]);
                        p1[j] = fmaf(h1, w2s[n][j], p1[j]);
                    }
                }
            }
        }
        #pragma unroll
        for (int mask = 2; mask >= 1; mask >>= 1) {
            #pragma unroll
            for (int j = 0; j < 10; j++) {
                p0[j] += __shfl_xor_sync(0xffffffffu, p0[j], mask);
                p1[j] += __shfl_xor_sync(0xffffffffu, p1[j], mask);
            }
        }
        if (qid == 0) {
            int r0 = mbase + qrow;
            int r1 = r0 + 8;
            if (r0 < Brows) {
                #pragma unroll
                for (int j = 0; j < 10; j++)
                    out[(size_t)r0 * 10 + j] = p0[j] + b2v[j];
            }
            if (r1 < Brows) {
                #pragma unroll
                for (int j = 0; j < 10; j++)
                    out[(size_t)r1 * 10 + j] = p1[j] + b2v[j];
            }
        }
    }
}

// ---------------- launch ---------------------------------------------------

extern "C" void kernel_launch(void* const* d_in, const int* in_sizes, int n_in,
                              void* d_out, int out_size) {
    const float* x      = (const float*)d_in[0];
    const float* conv_w = (const float*)d_in[1];
    const float* fc1_w  = (const float*)d_in[2];
    const float* fc1_b  = (const float*)d_in[3];
    const float* fc2_w  = (const float*)d_in[4];
    const float* fc2_b  = (const float*)d_in[5];
    float* out = (float*)d_out;

    int Brows = in_sizes[0] / KW;

    build_w1<<<(104 * KW + 255) / 256, 256>>>(conv_w, fc1_w);

    cudaFuncSetAttribute(fused_gemm, cudaFuncAttributeMaxDynamicSharedMemorySize,
                         BSMEM);

    fused_gemm<<<148, CTA_T, BSMEM>>>(x, fc1_b, fc2_w, fc2_b, out, Brows);
}